// round 14
// baseline (speedup 1.0000x reference)
#include <cuda_runtime.h>
#include <cuda_fp16.h>
#include <cstdint>

#define N_NODES 8192
#define IN_F    256
#define OUT_F   128
#define ALPHA   0.2f

// ---------------- device scratch (no allocations allowed) ----------------
__device__ __half g_hh[N_NODES * OUT_F];   // fp16 h
__device__ float  g_s1[N_NODES], g_s2[N_NODES];
__device__ float  g_E1[N_NODES], g_E2[N_NODES];
__device__ float  g_F1[N_NODES], g_F2[N_NODES];

// ---------------- helpers ----------------
__device__ __forceinline__ uint32_t smem_u32(const void* p) {
    uint32_t r;
    asm("{ .reg .u64 t; cvta.to.shared.u64 t, %1; cvt.u32.u64 %0, t; }" : "=r"(r) : "l"(p));
    return r;
}
__device__ __forceinline__ void cpa16(uint32_t dst, const void* src) {
    asm volatile("cp.async.cg.shared.global [%0], [%1], 16;" :: "r"(dst), "l"(src) : "memory");
}
__device__ __forceinline__ void cpa_commit() {
    asm volatile("cp.async.commit_group;" ::: "memory");
}
__device__ __forceinline__ void ldm_x4(uint32_t* r, uint32_t addr) {
    asm volatile("ldmatrix.sync.aligned.m8n8.x4.shared.b16 {%0,%1,%2,%3}, [%4];"
                 : "=r"(r[0]), "=r"(r[1]), "=r"(r[2]), "=r"(r[3]) : "r"(addr));
}
__device__ __forceinline__ void ldm_x4_t(uint32_t* r, uint32_t addr) {
    asm volatile("ldmatrix.sync.aligned.m8n8.x4.trans.shared.b16 {%0,%1,%2,%3}, [%4];"
                 : "=r"(r[0]), "=r"(r[1]), "=r"(r[2]), "=r"(r[3]) : "r"(addr));
}
__device__ __forceinline__ void mma_f16(float* d, const uint32_t* a, const uint32_t* b) {
    asm volatile(
        "mma.sync.aligned.m16n8k16.row.col.f32.f16.f16.f32 "
        "{%0,%1,%2,%3}, {%4,%5,%6,%7}, {%8,%9}, {%0,%1,%2,%3};"
        : "+f"(d[0]), "+f"(d[1]), "+f"(d[2]), "+f"(d[3])
        : "r"(a[0]), "r"(a[1]), "r"(a[2]), "r"(a[3]), "r"(b[0]), "r"(b[1]));
}
// partial named barriers: producers (256) + one consumer group (128) = 384
__device__ __forceinline__ void bar_sync384(int id)   {
    asm volatile("bar.sync %0, 384;" :: "r"(id) : "memory");
}
__device__ __forceinline__ void bar_arrive384(int id) {
    asm volatile("bar.arrive %0, 384;" :: "r"(id) : "memory");
}

// ========= Kernel 1: h = x @ W, fused s1/s2/exp factors + fp16 h =========
__global__ void __launch_bounds__(256) h_gemm_kernel(const float* __restrict__ x,
                                                     const float* __restrict__ W,
                                                     const float* __restrict__ a) {
    __shared__ float xs[32][36];
    __shared__ __align__(16) float Ws[32][OUT_F];

    const int tid = threadIdx.x;
    const int tx  = tid & 31;
    const int ty  = tid >> 5;
    const int m0  = blockIdx.x * 32;

    float acc[4][4];
    #pragma unroll
    for (int r = 0; r < 4; r++)
        #pragma unroll
        for (int c = 0; c < 4; c++) acc[r][c] = 0.f;

    for (int kt = 0; kt < IN_F; kt += 32) {
        {
            const int row = tid >> 3, c = (tid & 7) * 4;
            *(float4*)&xs[row][c] = *(const float4*)&x[(size_t)(m0 + row) * IN_F + kt + c];
        }
        #pragma unroll
        for (int q = 0; q < 4; q++) {
            const int idx = tid + 256 * q;
            const int row = idx >> 5, c = (idx & 31) * 4;
            *(float4*)&Ws[row][c] = *(const float4*)&W[(size_t)(kt + row) * OUT_F + c];
        }
        __syncthreads();

        #pragma unroll
        for (int kk = 0; kk < 32; kk++) {
            float4 b = *(const float4*)&Ws[kk][tx * 4];
            #pragma unroll
            for (int r = 0; r < 4; r++) {
                float av = xs[ty * 4 + r][kk];
                acc[r][0] = fmaf(av, b.x, acc[r][0]);
                acc[r][1] = fmaf(av, b.y, acc[r][1]);
                acc[r][2] = fmaf(av, b.z, acc[r][2]);
                acc[r][3] = fmaf(av, b.w, acc[r][3]);
            }
        }
        __syncthreads();
    }

    #pragma unroll
    for (int r = 0; r < 4; r++) {
        __half2 h0 = __floats2half2_rn(acc[r][0], acc[r][1]);
        __half2 h1 = __floats2half2_rn(acc[r][2], acc[r][3]);
        *(uint2*)&g_hh[(size_t)(m0 + ty * 4 + r) * OUT_F + tx * 4] =
            make_uint2(*(uint32_t*)&h0, *(uint32_t*)&h1);
    }

    float a1v[4], a2v[4];
    *(float4*)a1v = __ldg((const float4*)&a[tx * 4]);
    *(float4*)a2v = __ldg((const float4*)&a[OUT_F + tx * 4]);
    float s1p[4], s2p[4];
    #pragma unroll
    for (int r = 0; r < 4; r++) {
        s1p[r] = acc[r][0]*a1v[0] + acc[r][1]*a1v[1] + acc[r][2]*a1v[2] + acc[r][3]*a1v[3];
        s2p[r] = acc[r][0]*a2v[0] + acc[r][1]*a2v[1] + acc[r][2]*a2v[2] + acc[r][3]*a2v[3];
    }
    #pragma unroll
    for (int o = 16; o; o >>= 1) {
        #pragma unroll
        for (int r = 0; r < 4; r++) {
            s1p[r] += __shfl_xor_sync(0xffffffffu, s1p[r], o);
            s2p[r] += __shfl_xor_sync(0xffffffffu, s2p[r], o);
        }
    }
    if (tx < 4) {
        const int row = m0 + ty * 4 + tx;
        const float s1 = s1p[tx], s2 = s2p[tx];
        g_s1[row] = s1;               g_s2[row] = s2;
        g_E1[row] = expf(s1);         g_E2[row] = expf(s2);
        g_F1[row] = expf(ALPHA * s1); g_F2[row] = expf(ALPHA * s2);
    }
}

// ====== Kernel 2: warp-specialized, two consumer parity groups ======
// 512 threads. Warps 0-3: consumer group A (even windows), 4-7: group B (odd),
// each warp 64x32 tile per K-tile. Warps 8-15: producers (unchanged machinery).
// Parity-split 384-thread barriers: full 1,2 / free 3,4. K-partials merged via smem.
#define ADJ_ST   9216          // 64 rows * 144B
#define H_ST     8704          // 32 rows * 272B
#define SEF_ST   384
#define PS_ST    5120          // 64 rows * 80B
#define OFF_ADJ  0
#define OFF_H    73728         // 8*9216
#define OFF_SEF  143360        // +8*8704
#define OFF_PS   146432        // +8*384
#define OFF_Z    166912        // +4*5120
#define SMEM_SZ  167168

// producer load of one tile's worth (ptid = 0..255)
__device__ __forceinline__ void load_stage(uint32_t sbase, int st, int j0, int m0,
                                           const float* __restrict__ adj, int ptid) {
    {
        const uint32_t adst = sbase + OFF_ADJ + st * ADJ_ST;
        const float* asrc = adj + (size_t)m0 * N_NODES + j0;
        #pragma unroll
        for (int q = 0; q < 2; q++) {
            const int ch = ptid * 2 + q;
            cpa16(adst + (uint32_t)(ch >> 3) * 144 + (uint32_t)(ch & 7) * 16,
                  asrc + (size_t)(ch >> 3) * N_NODES + (ch & 7) * 4);
        }
    }
    {
        const uint32_t hdst = sbase + OFF_H + st * H_ST;
        const __half* hsrc = g_hh + (size_t)j0 * OUT_F;
        #pragma unroll
        for (int q = 0; q < 2; q++) {
            const int ch = ptid * 2 + q;
            cpa16(hdst + (uint32_t)(ch >> 4) * 272 + (uint32_t)(ch & 15) * 16,
                  hsrc + (ch >> 4) * OUT_F + (ch & 15) * 8);
        }
    }
    if (ptid < 24) {
        const int arr = ptid >> 3, ch = ptid & 7;
        const float* s = (arr == 0) ? g_s2 : (arr == 1) ? g_E2 : g_F2;
        cpa16(sbase + OFF_SEF + st * SEF_ST + arr * 128 + ch * 16, s + j0 + ch * 4);
    }
}

__global__ void __launch_bounds__(512, 1) gat_mma_kernel(const float* __restrict__ adj,
                                                         float* __restrict__ out) {
    extern __shared__ __align__(16) char smem[];
    const uint32_t sbase = smem_u32(smem);
    float* Zs = (float*)(smem + OFF_Z);

    const int tid  = threadIdx.x;
    const int lane = tid & 31;
    const int w    = tid >> 5;
    const int m0   = blockIdx.x * 64;

    if (w >= 8) {
        // ======================= PRODUCER =======================
        const int ptid = tid - 256;
        const int br   = ptid >> 2;          // row 0..63
        const int c0b  = (ptid & 3) * 8;     // 8 cols

        const float s1v = __ldg(&g_s1[m0 + br]);
        const float E1v = __ldg(&g_E1[m0 + br]);
        const float F1v = __ldg(&g_F1[m0 + br]);

        #pragma unroll
        for (int ww = 0; ww < 2; ww++) {
            load_stage(sbase, 2 * ww,     (2 * ww) * 32,     m0, adj, ptid);
            load_stage(sbase, 2 * ww + 1, (2 * ww + 1) * 32, m0, adj, ptid);
            cpa_commit();
        }

        float z_acc = 0.f;

        for (int wnd = 0; wnd < 128; ++wnd) {
            const int slot = wnd & 1;
            if (wnd >= 2) bar_sync384(3 + slot);         // group(slot) freed window wnd-2

            if (wnd + 2 < 128) {
                const int t = 2 * wnd + 4;
                load_stage(sbase, t & 7,       t * 32,       m0, adj, ptid);
                load_stage(sbase, (t + 1) & 7, (t + 1) * 32, m0, adj, ptid);
                cpa_commit();
                asm volatile("cp.async.wait_group 2;" ::: "memory");
            } else {
                asm volatile("cp.async.wait_group 0;" ::: "memory");
            }

            #pragma unroll
            for (int ti = 0; ti < 2; ti++) {
                const int t  = 2 * wnd + ti;
                const int st = t & 7;
                const float* adjS = (const float*)(smem + OFF_ADJ + st * ADJ_ST) + br * 36 + c0b;
                const float* sefS = (const float*)(smem + OFF_SEF + st * SEF_ST);
                float av[8], s2v[8], E2v[8], F2v[8];
                *(float4*)&av[0]  = *(const float4*)adjS;
                *(float4*)&av[4]  = *(const float4*)(adjS + 4);
                *(float4*)&s2v[0] = *(const float4*)(sefS + c0b);
                *(float4*)&s2v[4] = *(const float4*)(sefS + c0b + 4);
                *(float4*)&E2v[0] = *(const float4*)(sefS + 32 + c0b);
                *(float4*)&E2v[4] = *(const float4*)(sefS + 32 + c0b + 4);
                *(float4*)&F2v[0] = *(const float4*)(sefS + 64 + c0b);
                *(float4*)&F2v[4] = *(const float4*)(sefS + 64 + c0b + 4);
                float p[8];
                #pragma unroll
                for (int q = 0; q < 8; q++) {
                    float tt = s1v + s2v[q];
                    float e  = (tt >= 0.f) ? (E1v * E2v[q]) : (F1v * F2v[q]);
                    p[q] = (av[q] > 0.f) ? e : 0.f;
                    z_acc += p[q];
                }
                uint32_t pp[4];
                #pragma unroll
                for (int q = 0; q < 4; q++) {
                    __half2 hh = __floats2half2_rn(p[q * 2], p[q * 2 + 1]);
                    pp[q] = *(uint32_t*)&hh;
                }
                *(uint4*)(smem + OFF_PS + (t & 3) * PS_ST + br * 80 + c0b * 2) =
                    make_uint4(pp[0], pp[1], pp[2], pp[3]);
            }
            bar_arrive384(1 + slot);                     // signal window full to group(slot)
        }

        z_acc += __shfl_xor_sync(0xffffffffu, z_acc, 1);
        z_acc += __shfl_xor_sync(0xffffffffu, z_acc, 2);
        if ((ptid & 3) == 0) Zs[br] = z_acc;
        __syncthreads();                                 // sync #1
        // producers done (group B finishes stores after sync)
    } else {
        // ================== CONSUMER (two parity groups) ==================
        const int wn  = w & 3;           // N 32-quarter
        const int par = w >> 2;          // 0: even windows, 1: odd windows
        const int gq  = lane >> 2;
        const int tg  = lane & 3;

        const uint32_t a_base = (uint32_t)(lane & 15) * 80u + (uint32_t)(lane >> 4) * 16u;
        const uint32_t b_base = (uint32_t)(lane & 15) * 272u
                              + (uint32_t)(wn * 32 + (lane >> 4) * 8) * 2u;

        float acc[4][4][4];              // [am 16-row block][nt 8-col block][frag]
        #pragma unroll
        for (int am = 0; am < 4; am++)
            #pragma unroll
            for (int nt = 0; nt < 4; nt++)
                #pragma unroll
                for (int i = 0; i < 4; i++) acc[am][nt][i] = 0.f;

        for (int wnd = par; wnd < 128; wnd += 2) {
            bar_sync384(1 + par);                        // window data ready

            #pragma unroll
            for (int ti = 0; ti < 2; ti++) {
                const int t = 2 * wnd + ti;
                const uint32_t pa = sbase + OFF_PS + (uint32_t)(t & 3) * PS_ST + a_base;
                const uint32_t hb = sbase + OFF_H + (uint32_t)(t & 7) * H_ST + b_base;

                #pragma unroll
                for (int k16 = 0; k16 < 2; k16++) {
                    uint32_t afr[4][4];
                    #pragma unroll
                    for (int am = 0; am < 4; am++)
                        ldm_x4(afr[am], pa + (uint32_t)am * 1280u + (uint32_t)k16 * 32u);
                    uint32_t bfr[2][4];
                    #pragma unroll
                    for (int np = 0; np < 2; np++)
                        ldm_x4_t(bfr[np], hb + (uint32_t)k16 * 4352u + (uint32_t)np * 32u);
                    #pragma unroll
                    for (int am = 0; am < 4; am++)
                        #pragma unroll
                        for (int nt = 0; nt < 4; nt++)
                            mma_f16(acc[am][nt], afr[am], &bfr[nt >> 1][(nt & 1) * 2]);
                }
            }
            bar_arrive384(3 + par);                      // release window
        }

        float* mrg = (float*)(smem + OFF_ADJ);           // 64 x 132 fp32 (dead adj stages)
        if (par == 0) {
            #pragma unroll
            for (int am = 0; am < 4; am++) {
                const int r0 = am * 16 + gq;
                #pragma unroll
                for (int nt = 0; nt < 4; nt++) {
                    const int c = wn * 32 + nt * 8 + tg * 2;
                    mrg[r0 * 132 + c]           = acc[am][nt][0];
                    mrg[r0 * 132 + c + 1]       = acc[am][nt][1];
                    mrg[(r0 + 8) * 132 + c]     = acc[am][nt][2];
                    mrg[(r0 + 8) * 132 + c + 1] = acc[am][nt][3];
                }
            }
        }
        __syncthreads();                                 // sync #1 (with producers)
        if (par == 1) {
            #pragma unroll
            for (int am = 0; am < 4; am++) {
                const int rl0 = am * 16 + gq;
                const float zi0 = 1.0f / Zs[rl0];
                const float zi1 = 1.0f / Zs[rl0 + 8];
                const int r = m0 + rl0;
                #pragma unroll
                for (int nt = 0; nt < 4; nt++) {
                    const int c = wn * 32 + nt * 8 + tg * 2;
                    float v0 = (acc[am][nt][0] + mrg[rl0 * 132 + c])           * zi0;
                    float v1 = (acc[am][nt][1] + mrg[rl0 * 132 + c + 1])       * zi0;
                    float v2 = (acc[am][nt][2] + mrg[(rl0 + 8) * 132 + c])     * zi1;
                    float v3 = (acc[am][nt][3] + mrg[(rl0 + 8) * 132 + c + 1]) * zi1;
                    *(float2*)&out[(size_t)r * OUT_F + c]       = make_float2(v0, v1);
                    *(float2*)&out[(size_t)(r + 8) * OUT_F + c] = make_float2(v2, v3);
                }
            }
        }
    }
}

// ============================ launch =============================
extern "C" void kernel_launch(void* const* d_in, const int* in_sizes, int n_in,
                              void* d_out, int out_size) {
    const float *x = nullptr, *adj = nullptr, *W = nullptr, *a = nullptr;
    for (int i = 0; i < n_in; i++) {
        switch (in_sizes[i]) {
            case N_NODES * IN_F:  x   = (const float*)d_in[i]; break;
            case 67108864:        adj = (const float*)d_in[i]; break;
            case IN_F * OUT_F:    W   = (const float*)d_in[i]; break;
            case 2 * OUT_F:       a   = (const float*)d_in[i]; break;
            default: break;
        }
    }
    if (!x)   x   = (const float*)d_in[0];
    if (!adj) adj = (const float*)d_in[1];
    if (!W)   W   = (const float*)d_in[2];
    if (!a)   a   = (const float*)d_in[3];
    float* out = (float*)d_out;

    h_gemm_kernel<<<N_NODES / 32, 256>>>(x, W, a);

    cudaFuncSetAttribute(gat_mma_kernel, cudaFuncAttributeMaxDynamicSharedMemorySize, SMEM_SZ);
    gat_mma_kernel<<<N_NODES / 64, 512, SMEM_SZ>>>(adj, out);
}

// round 16
// speedup vs baseline: 1.0860x; 1.0860x over previous
#include <cuda_runtime.h>
#include <cuda_fp16.h>
#include <cstdint>

#define N_NODES 8192
#define IN_F    256
#define OUT_F   128
#define ALPHA   0.2f

// ---------------- device scratch (no allocations allowed) ----------------
__device__ __half g_hh[N_NODES * OUT_F];   // fp16 h
__device__ float  g_s1[N_NODES], g_s2[N_NODES];
__device__ float  g_E1[N_NODES], g_E2[N_NODES];
__device__ float  g_F1[N_NODES], g_F2[N_NODES];

// ---------------- helpers ----------------
__device__ __forceinline__ uint32_t smem_u32(const void* p) {
    uint32_t r;
    asm("{ .reg .u64 t; cvta.to.shared.u64 t, %1; cvt.u32.u64 %0, t; }" : "=r"(r) : "l"(p));
    return r;
}
__device__ __forceinline__ void cpa16(uint32_t dst, const void* src) {
    asm volatile("cp.async.cg.shared.global [%0], [%1], 16;" :: "r"(dst), "l"(src) : "memory");
}
__device__ __forceinline__ void cpa_commit() {
    asm volatile("cp.async.commit_group;" ::: "memory");
}
__device__ __forceinline__ void ldm_x4(uint32_t* r, uint32_t addr) {
    asm volatile("ldmatrix.sync.aligned.m8n8.x4.shared.b16 {%0,%1,%2,%3}, [%4];"
                 : "=r"(r[0]), "=r"(r[1]), "=r"(r[2]), "=r"(r[3]) : "r"(addr));
}
__device__ __forceinline__ void ldm_x4_t(uint32_t* r, uint32_t addr) {
    asm volatile("ldmatrix.sync.aligned.m8n8.x4.trans.shared.b16 {%0,%1,%2,%3}, [%4];"
                 : "=r"(r[0]), "=r"(r[1]), "=r"(r[2]), "=r"(r[3]) : "r"(addr));
}
__device__ __forceinline__ void mma_f16(float* d, const uint32_t* a, const uint32_t* b) {
    asm volatile(
        "mma.sync.aligned.m16n8k16.row.col.f32.f16.f16.f32 "
        "{%0,%1,%2,%3}, {%4,%5,%6,%7}, {%8,%9}, {%0,%1,%2,%3};"
        : "+f"(d[0]), "+f"(d[1]), "+f"(d[2]), "+f"(d[3])
        : "r"(a[0]), "r"(a[1]), "r"(a[2]), "r"(a[3]), "r"(b[0]), "r"(b[1]));
}
__device__ __forceinline__ void bar_sync_n(int id, int n)   {
    asm volatile("bar.sync %0, %1;" :: "r"(id), "r"(n) : "memory");
}
__device__ __forceinline__ void bar_arrive_n(int id, int n) {
    asm volatile("bar.arrive %0, %1;" :: "r"(id), "r"(n) : "memory");
}

// ========= Kernel 1: h = x @ W, fused s1/s2/exp factors + fp16 h =========
__global__ void __launch_bounds__(256) h_gemm_kernel(const float* __restrict__ x,
                                                     const float* __restrict__ W,
                                                     const float* __restrict__ a) {
    __shared__ float xs[32][36];
    __shared__ __align__(16) float Ws[32][OUT_F];

    const int tid = threadIdx.x;
    const int tx  = tid & 31;
    const int ty  = tid >> 5;
    const int m0  = blockIdx.x * 32;

    float acc[4][4];
    #pragma unroll
    for (int r = 0; r < 4; r++)
        #pragma unroll
        for (int c = 0; c < 4; c++) acc[r][c] = 0.f;

    for (int kt = 0; kt < IN_F; kt += 32) {
        {
            const int row = tid >> 3, c = (tid & 7) * 4;
            *(float4*)&xs[row][c] = *(const float4*)&x[(size_t)(m0 + row) * IN_F + kt + c];
        }
        #pragma unroll
        for (int q = 0; q < 4; q++) {
            const int idx = tid + 256 * q;
            const int row = idx >> 5, c = (idx & 31) * 4;
            *(float4*)&Ws[row][c] = *(const float4*)&W[(size_t)(kt + row) * OUT_F + c];
        }
        __syncthreads();

        #pragma unroll
        for (int kk = 0; kk < 32; kk++) {
            float4 b = *(const float4*)&Ws[kk][tx * 4];
            #pragma unroll
            for (int r = 0; r < 4; r++) {
                float av = xs[ty * 4 + r][kk];
                acc[r][0] = fmaf(av, b.x, acc[r][0]);
                acc[r][1] = fmaf(av, b.y, acc[r][1]);
                acc[r][2] = fmaf(av, b.z, acc[r][2]);
                acc[r][3] = fmaf(av, b.w, acc[r][3]);
            }
        }
        __syncthreads();
    }

    #pragma unroll
    for (int r = 0; r < 4; r++) {
        __half2 h0 = __floats2half2_rn(acc[r][0], acc[r][1]);
        __half2 h1 = __floats2half2_rn(acc[r][2], acc[r][3]);
        *(uint2*)&g_hh[(size_t)(m0 + ty * 4 + r) * OUT_F + tx * 4] =
            make_uint2(*(uint32_t*)&h0, *(uint32_t*)&h1);
    }

    float a1v[4], a2v[4];
    *(float4*)a1v = __ldg((const float4*)&a[tx * 4]);
    *(float4*)a2v = __ldg((const float4*)&a[OUT_F + tx * 4]);
    float s1p[4], s2p[4];
    #pragma unroll
    for (int r = 0; r < 4; r++) {
        s1p[r] = acc[r][0]*a1v[0] + acc[r][1]*a1v[1] + acc[r][2]*a1v[2] + acc[r][3]*a1v[3];
        s2p[r] = acc[r][0]*a2v[0] + acc[r][1]*a2v[1] + acc[r][2]*a2v[2] + acc[r][3]*a2v[3];
    }
    #pragma unroll
    for (int o = 16; o; o >>= 1) {
        #pragma unroll
        for (int r = 0; r < 4; r++) {
            s1p[r] += __shfl_xor_sync(0xffffffffu, s1p[r], o);
            s2p[r] += __shfl_xor_sync(0xffffffffu, s2p[r], o);
        }
    }
    if (tx < 4) {
        const int row = m0 + ty * 4 + tx;
        const float s1 = s1p[tx], s2 = s2p[tx];
        g_s1[row] = s1;               g_s2[row] = s2;
        g_E1[row] = expf(s1);         g_E2[row] = expf(s2);
        g_F1[row] = expf(ALPHA * s1); g_F2[row] = expf(ALPHA * s2);
    }
}

// ====== Kernel 2: warp-specialized, 768 threads (8 consumer + 16 producer warps) ======
// Warps 0-7: MMA consumers. Warps 8-23: producers.
// Bars: full 1,2 (count 768) / free 3,4 (count 768) / producer-order 5 (count 512).
// Bar 5 publishes the sef strips (issued by ptid<24 only) to all producers —
// cp.async completion is per-issuing-thread; without this, sef reads race.
#define ADJ_ST   9216          // 64 rows * 144B
#define H_ST     8704          // 32 rows * 272B
#define SEF_ST   384
#define PS_ST    5120          // 64 rows * 80B
#define OFF_ADJ  0
#define OFF_H    73728         // 8*9216
#define OFF_SEF  143360        // +8*8704
#define OFF_PS   146432        // +8*384
#define OFF_Z    166912        // +4*5120
#define SMEM_SZ  167168

// producer load of one tile's worth (ptid = 0..511)
__device__ __forceinline__ void load_stage(uint32_t sbase, int st, int j0, int m0,
                                           const float* __restrict__ adj, int ptid) {
    // adj: 64 rows x 128B @144B stride -> 512 chunks, 1/thread
    // (each thread later builds exactly the 4 cols it copied -> self-consistent)
    {
        const uint32_t adst = sbase + OFF_ADJ + st * ADJ_ST;
        const float* asrc = adj + (size_t)m0 * N_NODES + j0;
        cpa16(adst + (uint32_t)(ptid >> 3) * 144 + (uint32_t)(ptid & 7) * 16,
              asrc + (size_t)(ptid >> 3) * N_NODES + (ptid & 7) * 4);
    }
    // h: 32 rows x 256B @272B stride -> 512 chunks, 1/thread (consumers ordered by full bar)
    {
        const uint32_t hdst = sbase + OFF_H + st * H_ST;
        const __half* hsrc = g_hh + (size_t)j0 * OUT_F;
        cpa16(hdst + (uint32_t)(ptid >> 4) * 272 + (uint32_t)(ptid & 15) * 16,
              hsrc + (ptid >> 4) * OUT_F + (ptid & 15) * 8);
    }
    // s2/E2/F2 strips (issued by ptid<24; published to producers via bar 5)
    if (ptid < 24) {
        const int arr = ptid >> 3, ch = ptid & 7;
        const float* s = (arr == 0) ? g_s2 : (arr == 1) ? g_E2 : g_F2;
        cpa16(sbase + OFF_SEF + st * SEF_ST + arr * 128 + ch * 16, s + j0 + ch * 4);
    }
}

__global__ void __launch_bounds__(768, 1) gat_mma_kernel(const float* __restrict__ adj,
                                                         float* __restrict__ out) {
    extern __shared__ __align__(16) char smem[];
    const uint32_t sbase = smem_u32(smem);
    float* Zs = (float*)(smem + OFF_Z);

    const int tid  = threadIdx.x;
    const int lane = tid & 31;
    const int w    = tid >> 5;
    const int m0   = blockIdx.x * 64;

    if (w >= 8) {
        // ======================= PRODUCER (16 warps) =======================
        const int ptid = tid - 256;          // 0..511
        const int br   = ptid >> 3;          // row 0..63
        const int c0b  = (ptid & 7) * 4;     // 4 cols

        const float s1v = __ldg(&g_s1[m0 + br]);
        const float E1v = __ldg(&g_E1[m0 + br]);
        const float F1v = __ldg(&g_F1[m0 + br]);

        // prologue: windows 0,1 (tiles 0..3), one commit per window
        #pragma unroll
        for (int ww = 0; ww < 2; ww++) {
            load_stage(sbase, 2 * ww,     (2 * ww) * 32,     m0, adj, ptid);
            load_stage(sbase, 2 * ww + 1, (2 * ww + 1) * 32, m0, adj, ptid);
            cpa_commit();
        }

        float z_acc = 0.f;

        for (int wnd = 0; wnd < 128; ++wnd) {
            const int slot = wnd & 1;
            if (wnd >= 2) bar_sync_n(3 + slot, 768);     // consumers freed window wnd-2

            if (wnd + 2 < 128) {
                const int t = 2 * wnd + 4;
                load_stage(sbase, t & 7,       t * 32,       m0, adj, ptid);
                load_stage(sbase, (t + 1) & 7, (t + 1) * 32, m0, adj, ptid);
                cpa_commit();
                asm volatile("cp.async.wait_group 2;" ::: "memory");
            } else {
                asm volatile("cp.async.wait_group 0;" ::: "memory");
            }

            // producer-order barrier: publishes sef (copied by ptid<24) to all producers
            bar_sync_n(5, 512);

            // build both tiles of this window (4 cols per thread)
            #pragma unroll
            for (int ti = 0; ti < 2; ti++) {
                const int t  = 2 * wnd + ti;
                const int st = t & 7;
                const float* adjS = (const float*)(smem + OFF_ADJ + st * ADJ_ST) + br * 36 + c0b;
                const float* sefS = (const float*)(smem + OFF_SEF + st * SEF_ST);
                float4 av4 = *(const float4*)adjS;
                float4 s24 = *(const float4*)(sefS + c0b);
                float4 E24 = *(const float4*)(sefS + 32 + c0b);
                float4 F24 = *(const float4*)(sefS + 64 + c0b);
                float av[4]  = {av4.x, av4.y, av4.z, av4.w};
                float s2v[4] = {s24.x, s24.y, s24.z, s24.w};
                float E2v[4] = {E24.x, E24.y, E24.z, E24.w};
                float F2v[4] = {F24.x, F24.y, F24.z, F24.w};
                float p[4];
                #pragma unroll
                for (int q = 0; q < 4; q++) {
                    float tt = s1v + s2v[q];
                    float e  = (tt >= 0.f) ? (E1v * E2v[q]) : (F1v * F2v[q]);
                    p[q] = (av[q] > 0.f) ? e : 0.f;
                    z_acc += p[q];
                }
                __half2 h0 = __floats2half2_rn(p[0], p[1]);
                __half2 h1 = __floats2half2_rn(p[2], p[3]);
                *(uint2*)(smem + OFF_PS + (t & 3) * PS_ST + br * 80 + c0b * 2) =
                    make_uint2(*(uint32_t*)&h0, *(uint32_t*)&h1);
            }
            bar_arrive_n(1 + slot, 768);                 // signal window full
        }

        // Z reduce (8 lanes per row)
        z_acc += __shfl_xor_sync(0xffffffffu, z_acc, 1);
        z_acc += __shfl_xor_sync(0xffffffffu, z_acc, 2);
        z_acc += __shfl_xor_sync(0xffffffffu, z_acc, 4);
        if ((ptid & 7) == 0) Zs[br] = z_acc;
    } else {
        // ======================= CONSUMER (8 warps) =======================
        const int wm = w >> 2;           // M 32-half
        const int wn = w & 3;            // N 32-quarter
        const int gq = lane >> 2;
        const int tg = lane & 3;

        const uint32_t a_base = (uint32_t)(wm * 32 + (lane & 15)) * 80u
                              + (uint32_t)(lane >> 4) * 16u;
        const uint32_t b_base = (uint32_t)(lane & 15) * 272u
                              + (uint32_t)(wn * 32 + (lane >> 4) * 8) * 2u;

        float acc[2][4][4];
        #pragma unroll
        for (int mt = 0; mt < 2; mt++)
            #pragma unroll
            for (int nt = 0; nt < 4; nt++)
                #pragma unroll
                for (int i = 0; i < 4; i++) acc[mt][nt][i] = 0.f;

        for (int wnd = 0; wnd < 128; ++wnd) {
            const int slot = wnd & 1;
            bar_sync_n(1 + slot, 768);                   // window data ready

            #pragma unroll
            for (int ti = 0; ti < 2; ti++) {
                const int t = 2 * wnd + ti;
                const uint32_t pa = sbase + OFF_PS + (uint32_t)(t & 3) * PS_ST + a_base;
                const uint32_t hb = sbase + OFF_H + (uint32_t)(t & 7) * H_ST + b_base;

                #pragma unroll
                for (int k16 = 0; k16 < 2; k16++) {
                    uint32_t afr[2][4];
                    #pragma unroll
                    for (int mt = 0; mt < 2; mt++)
                        ldm_x4(afr[mt], pa + (uint32_t)mt * 1280u + (uint32_t)k16 * 32u);
                    uint32_t bfr[2][4];
                    #pragma unroll
                    for (int np = 0; np < 2; np++)
                        ldm_x4_t(bfr[np], hb + (uint32_t)k16 * 4352u + (uint32_t)np * 32u);
                    #pragma unroll
                    for (int mt = 0; mt < 2; mt++)
                        #pragma unroll
                        for (int nt = 0; nt < 4; nt++)
                            mma_f16(acc[mt][nt], afr[mt], &bfr[nt >> 1][(nt & 1) * 2]);
                }
            }
            bar_arrive_n(3 + slot, 768);                 // release window
        }

        __syncthreads();

        // epilogue: normalize + store (full K per warp — no merge)
        #pragma unroll
        for (int mt = 0; mt < 2; mt++) {
            const int rl0 = wm * 32 + mt * 16 + gq;
            const float zi0 = 1.0f / Zs[rl0];
            const float zi1 = 1.0f / Zs[rl0 + 8];
            const int r = m0 + rl0;
            #pragma unroll
            for (int nt = 0; nt < 4; nt++) {
                const int c = wn * 32 + nt * 8 + tg * 2;
                *(float2*)&out[(size_t)r * OUT_F + c] =
                    make_float2(acc[mt][nt][0] * zi0, acc[mt][nt][1] * zi0);
                *(float2*)&out[(size_t)(r + 8) * OUT_F + c] =
                    make_float2(acc[mt][nt][2] * zi1, acc[mt][nt][3] * zi1);
            }
        }
        return;
    }
    // producers fall through after Z write
    __syncthreads();
}

// ============================ launch =============================
extern "C" void kernel_launch(void* const* d_in, const int* in_sizes, int n_in,
                              void* d_out, int out_size) {
    const float *x = nullptr, *adj = nullptr, *W = nullptr, *a = nullptr;
    for (int i = 0; i < n_in; i++) {
        switch (in_sizes[i]) {
            case N_NODES * IN_F:  x   = (const float*)d_in[i]; break;
            case 67108864:        adj = (const float*)d_in[i]; break;
            case IN_F * OUT_F:    W   = (const float*)d_in[i]; break;
            case 2 * OUT_F:       a   = (const float*)d_in[i]; break;
            default: break;
        }
    }
    if (!x)   x   = (const float*)d_in[0];
    if (!adj) adj = (const float*)d_in[1];
    if (!W)   W   = (const float*)d_in[2];
    if (!a)   a   = (const float*)d_in[3];
    float* out = (float*)d_out;

    h_gemm_kernel<<<N_NODES / 32, 256>>>(x, W, a);

    cudaFuncSetAttribute(gat_mma_kernel, cudaFuncAttributeMaxDynamicSharedMemorySize, SMEM_SZ);
    gat_mma_kernel<<<N_NODES / 64, 768, SMEM_SZ>>>(adj, out);
}

// round 17
// speedup vs baseline: 1.0926x; 1.0061x over previous
#include <cuda_runtime.h>
#include <cuda_fp16.h>
#include <cstdint>

#define N_NODES 8192
#define IN_F    256
#define OUT_F   128
#define ALPHA   0.2f

// ---------------- device scratch (no allocations allowed) ----------------
__device__ __half g_hh[N_NODES * OUT_F];   // fp16 h
__device__ float  g_s1[N_NODES], g_s2[N_NODES];
__device__ float  g_E1[N_NODES], g_E2[N_NODES];
__device__ float  g_F1[N_NODES], g_F2[N_NODES];

// ---------------- helpers ----------------
__device__ __forceinline__ uint32_t smem_u32(const void* p) {
    uint32_t r;
    asm("{ .reg .u64 t; cvta.to.shared.u64 t, %1; cvt.u32.u64 %0, t; }" : "=r"(r) : "l"(p));
    return r;
}
__device__ __forceinline__ void cpa16(uint32_t dst, const void* src) {
    asm volatile("cp.async.cg.shared.global [%0], [%1], 16;" :: "r"(dst), "l"(src) : "memory");
}
__device__ __forceinline__ void cpa_commit() {
    asm volatile("cp.async.commit_group;" ::: "memory");
}
__device__ __forceinline__ void ldm_x4(uint32_t* r, uint32_t addr) {
    asm volatile("ldmatrix.sync.aligned.m8n8.x4.shared.b16 {%0,%1,%2,%3}, [%4];"
                 : "=r"(r[0]), "=r"(r[1]), "=r"(r[2]), "=r"(r[3]) : "r"(addr));
}
__device__ __forceinline__ void ldm_x4_t(uint32_t* r, uint32_t addr) {
    asm volatile("ldmatrix.sync.aligned.m8n8.x4.trans.shared.b16 {%0,%1,%2,%3}, [%4];"
                 : "=r"(r[0]), "=r"(r[1]), "=r"(r[2]), "=r"(r[3]) : "r"(addr));
}
__device__ __forceinline__ void mma_f16(float* d, const uint32_t* a, const uint32_t* b) {
    asm volatile(
        "mma.sync.aligned.m16n8k16.row.col.f32.f16.f16.f32 "
        "{%0,%1,%2,%3}, {%4,%5,%6,%7}, {%8,%9}, {%0,%1,%2,%3};"
        : "+f"(d[0]), "+f"(d[1]), "+f"(d[2]), "+f"(d[3])
        : "r"(a[0]), "r"(a[1]), "r"(a[2]), "r"(a[3]), "r"(b[0]), "r"(b[1]));
}
__device__ __forceinline__ void bar_sync_n(int id, int n)   {
    asm volatile("bar.sync %0, %1;" :: "r"(id), "r"(n) : "memory");
}
__device__ __forceinline__ void bar_arrive_n(int id, int n) {
    asm volatile("bar.arrive %0, %1;" :: "r"(id), "r"(n) : "memory");
}
// packed f32x2 (exact fp32 semantics, 2 MAC per instruction)
__device__ __forceinline__ unsigned long long packf2(float lo, float hi) {
    unsigned long long r;
    asm("mov.b64 %0, {%1, %2};" : "=l"(r) : "f"(lo), "f"(hi));
    return r;
}
__device__ __forceinline__ unsigned long long pack_dup(float v) {
    unsigned long long r;
    asm("mov.b64 %0, {%1, %1};" : "=l"(r) : "f"(v));
    return r;
}
__device__ __forceinline__ void fma2(unsigned long long &d,
                                     unsigned long long a_, unsigned long long b_) {
    asm("fma.rn.f32x2 %0, %1, %2, %0;" : "+l"(d) : "l"(a_), "l"(b_));
}
__device__ __forceinline__ void unpack2(unsigned long long v, float &lo, float &hi) {
    asm("mov.b64 {%0, %1}, %2;" : "=f"(lo), "=f"(hi) : "l"(v));
}

// ========= Kernel 1: h = x @ W (f32x2 packed), fused s1/s2/exp + fp16 h =========
__global__ void __launch_bounds__(256) h_gemm_kernel(const float* __restrict__ x,
                                                     const float* __restrict__ W,
                                                     const float* __restrict__ a) {
    __shared__ float xs_t[32][36];                 // transposed: [k][row]
    __shared__ __align__(16) float Ws[32][OUT_F];

    const int tid = threadIdx.x;
    const int tx  = tid & 31;
    const int ty  = tid >> 5;
    const int m0  = blockIdx.x * 32;

    unsigned long long acc2[4][2];
    #pragma unroll
    for (int r = 0; r < 4; r++) { acc2[r][0] = 0ull; acc2[r][1] = 0ull; }

    for (int kt = 0; kt < IN_F; kt += 32) {
        // x tile: load float4 row-major, store transposed
        {
            const int row = tid >> 3, c = (tid & 7) * 4;
            float4 v = *(const float4*)&x[(size_t)(m0 + row) * IN_F + kt + c];
            xs_t[c + 0][row] = v.x;
            xs_t[c + 1][row] = v.y;
            xs_t[c + 2][row] = v.z;
            xs_t[c + 3][row] = v.w;
        }
        #pragma unroll
        for (int q = 0; q < 4; q++) {
            const int idx = tid + 256 * q;
            const int row = idx >> 5, c = (idx & 31) * 4;
            *(float4*)&Ws[row][c] = *(const float4*)&W[(size_t)(kt + row) * OUT_F + c];
        }
        __syncthreads();

        #pragma unroll
        for (int kk = 0; kk < 32; kk++) {
            float4 b = *(const float4*)&Ws[kk][tx * 4];
            unsigned long long b01 = packf2(b.x, b.y);
            unsigned long long b23 = packf2(b.z, b.w);
            float4 av = *(const float4*)&xs_t[kk][ty * 4];   // broadcast LDS.128
            unsigned long long a0 = pack_dup(av.x);
            unsigned long long a1 = pack_dup(av.y);
            unsigned long long a2 = pack_dup(av.z);
            unsigned long long a3 = pack_dup(av.w);
            fma2(acc2[0][0], a0, b01); fma2(acc2[0][1], a0, b23);
            fma2(acc2[1][0], a1, b01); fma2(acc2[1][1], a1, b23);
            fma2(acc2[2][0], a2, b01); fma2(acc2[2][1], a2, b23);
            fma2(acc2[3][0], a3, b01); fma2(acc2[3][1], a3, b23);
        }
        __syncthreads();
    }

    // unpack accumulators
    float acc[4][4];
    #pragma unroll
    for (int r = 0; r < 4; r++) {
        unpack2(acc2[r][0], acc[r][0], acc[r][1]);
        unpack2(acc2[r][1], acc[r][2], acc[r][3]);
    }

    #pragma unroll
    for (int r = 0; r < 4; r++) {
        __half2 h0 = __floats2half2_rn(acc[r][0], acc[r][1]);
        __half2 h1 = __floats2half2_rn(acc[r][2], acc[r][3]);
        *(uint2*)&g_hh[(size_t)(m0 + ty * 4 + r) * OUT_F + tx * 4] =
            make_uint2(*(uint32_t*)&h0, *(uint32_t*)&h1);
    }

    float a1v[4], a2v[4];
    *(float4*)a1v = __ldg((const float4*)&a[tx * 4]);
    *(float4*)a2v = __ldg((const float4*)&a[OUT_F + tx * 4]);
    float s1p[4], s2p[4];
    #pragma unroll
    for (int r = 0; r < 4; r++) {
        s1p[r] = acc[r][0]*a1v[0] + acc[r][1]*a1v[1] + acc[r][2]*a1v[2] + acc[r][3]*a1v[3];
        s2p[r] = acc[r][0]*a2v[0] + acc[r][1]*a2v[1] + acc[r][2]*a2v[2] + acc[r][3]*a2v[3];
    }
    #pragma unroll
    for (int o = 16; o; o >>= 1) {
        #pragma unroll
        for (int r = 0; r < 4; r++) {
            s1p[r] += __shfl_xor_sync(0xffffffffu, s1p[r], o);
            s2p[r] += __shfl_xor_sync(0xffffffffu, s2p[r], o);
        }
    }
    if (tx < 4) {
        const int row = m0 + ty * 4 + tx;
        const float s1 = s1p[tx], s2 = s2p[tx];
        g_s1[row] = s1;               g_s2[row] = s2;
        g_E1[row] = expf(s1);         g_E2[row] = expf(s2);
        g_F1[row] = expf(ALPHA * s1); g_F2[row] = expf(ALPHA * s2);
    }
}

// ====== Kernel 2: warp-specialized, 768 threads (UNCHANGED from round 16) ======
#define ADJ_ST   9216
#define H_ST     8704
#define SEF_ST   384
#define PS_ST    5120
#define OFF_ADJ  0
#define OFF_H    73728
#define OFF_SEF  143360
#define OFF_PS   146432
#define OFF_Z    166912
#define SMEM_SZ  167168

__device__ __forceinline__ void load_stage(uint32_t sbase, int st, int j0, int m0,
                                           const float* __restrict__ adj, int ptid) {
    {
        const uint32_t adst = sbase + OFF_ADJ + st * ADJ_ST;
        const float* asrc = adj + (size_t)m0 * N_NODES + j0;
        cpa16(adst + (uint32_t)(ptid >> 3) * 144 + (uint32_t)(ptid & 7) * 16,
              asrc + (size_t)(ptid >> 3) * N_NODES + (ptid & 7) * 4);
    }
    {
        const uint32_t hdst = sbase + OFF_H + st * H_ST;
        const __half* hsrc = g_hh + (size_t)j0 * OUT_F;
        cpa16(hdst + (uint32_t)(ptid >> 4) * 272 + (uint32_t)(ptid & 15) * 16,
              hsrc + (ptid >> 4) * OUT_F + (ptid & 15) * 8);
    }
    if (ptid < 24) {
        const int arr = ptid >> 3, ch = ptid & 7;
        const float* s = (arr == 0) ? g_s2 : (arr == 1) ? g_E2 : g_F2;
        cpa16(sbase + OFF_SEF + st * SEF_ST + arr * 128 + ch * 16, s + j0 + ch * 4);
    }
}

__global__ void __launch_bounds__(768, 1) gat_mma_kernel(const float* __restrict__ adj,
                                                         float* __restrict__ out) {
    extern __shared__ __align__(16) char smem[];
    const uint32_t sbase = smem_u32(smem);
    float* Zs = (float*)(smem + OFF_Z);

    const int tid  = threadIdx.x;
    const int lane = tid & 31;
    const int w    = tid >> 5;
    const int m0   = blockIdx.x * 64;

    if (w >= 8) {
        // ======================= PRODUCER (16 warps) =======================
        const int ptid = tid - 256;
        const int br   = ptid >> 3;
        const int c0b  = (ptid & 7) * 4;

        const float s1v = __ldg(&g_s1[m0 + br]);
        const float E1v = __ldg(&g_E1[m0 + br]);
        const float F1v = __ldg(&g_F1[m0 + br]);

        #pragma unroll
        for (int ww = 0; ww < 2; ww++) {
            load_stage(sbase, 2 * ww,     (2 * ww) * 32,     m0, adj, ptid);
            load_stage(sbase, 2 * ww + 1, (2 * ww + 1) * 32, m0, adj, ptid);
            cpa_commit();
        }

        float z_acc = 0.f;

        for (int wnd = 0; wnd < 128; ++wnd) {
            const int slot = wnd & 1;
            if (wnd >= 2) bar_sync_n(3 + slot, 768);

            if (wnd + 2 < 128) {
                const int t = 2 * wnd + 4;
                load_stage(sbase, t & 7,       t * 32,       m0, adj, ptid);
                load_stage(sbase, (t + 1) & 7, (t + 1) * 32, m0, adj, ptid);
                cpa_commit();
                asm volatile("cp.async.wait_group 2;" ::: "memory");
            } else {
                asm volatile("cp.async.wait_group 0;" ::: "memory");
            }

            // publish sef (issued by ptid<24) to all producers
            bar_sync_n(5, 512);

            #pragma unroll
            for (int ti = 0; ti < 2; ti++) {
                const int t  = 2 * wnd + ti;
                const int st = t & 7;
                const float* adjS = (const float*)(smem + OFF_ADJ + st * ADJ_ST) + br * 36 + c0b;
                const float* sefS = (const float*)(smem + OFF_SEF + st * SEF_ST);
                float4 av4 = *(const float4*)adjS;
                float4 s24 = *(const float4*)(sefS + c0b);
                float4 E24 = *(const float4*)(sefS + 32 + c0b);
                float4 F24 = *(const float4*)(sefS + 64 + c0b);
                float av[4]  = {av4.x, av4.y, av4.z, av4.w};
                float s2v[4] = {s24.x, s24.y, s24.z, s24.w};
                float E2v[4] = {E24.x, E24.y, E24.z, E24.w};
                float F2v[4] = {F24.x, F24.y, F24.z, F24.w};
                float p[4];
                #pragma unroll
                for (int q = 0; q < 4; q++) {
                    float tt = s1v + s2v[q];
                    float e  = (tt >= 0.f) ? (E1v * E2v[q]) : (F1v * F2v[q]);
                    p[q] = (av[q] > 0.f) ? e : 0.f;
                    z_acc += p[q];
                }
                __half2 h0 = __floats2half2_rn(p[0], p[1]);
                __half2 h1 = __floats2half2_rn(p[2], p[3]);
                *(uint2*)(smem + OFF_PS + (t & 3) * PS_ST + br * 80 + c0b * 2) =
                    make_uint2(*(uint32_t*)&h0, *(uint32_t*)&h1);
            }
            bar_arrive_n(1 + slot, 768);
        }

        z_acc += __shfl_xor_sync(0xffffffffu, z_acc, 1);
        z_acc += __shfl_xor_sync(0xffffffffu, z_acc, 2);
        z_acc += __shfl_xor_sync(0xffffffffu, z_acc, 4);
        if ((ptid & 7) == 0) Zs[br] = z_acc;
    } else {
        // ======================= CONSUMER (8 warps) =======================
        const int wm = w >> 2;
        const int wn = w & 3;
        const int gq = lane >> 2;
        const int tg = lane & 3;

        const uint32_t a_base = (uint32_t)(wm * 32 + (lane & 15)) * 80u
                              + (uint32_t)(lane >> 4) * 16u;
        const uint32_t b_base = (uint32_t)(lane & 15) * 272u
                              + (uint32_t)(wn * 32 + (lane >> 4) * 8) * 2u;

        float acc[2][4][4];
        #pragma unroll
        for (int mt = 0; mt < 2; mt++)
            #pragma unroll
            for (int nt = 0; nt < 4; nt++)
                #pragma unroll
                for (int i = 0; i < 4; i++) acc[mt][nt][i] = 0.f;

        for (int wnd = 0; wnd < 128; ++wnd) {
            const int slot = wnd & 1;
            bar_sync_n(1 + slot, 768);

            #pragma unroll
            for (int ti = 0; ti < 2; ti++) {
                const int t = 2 * wnd + ti;
                const uint32_t pa = sbase + OFF_PS + (uint32_t)(t & 3) * PS_ST + a_base;
                const uint32_t hb = sbase + OFF_H + (uint32_t)(t & 7) * H_ST + b_base;

                #pragma unroll
                for (int k16 = 0; k16 < 2; k16++) {
                    uint32_t afr[2][4];
                    #pragma unroll
                    for (int mt = 0; mt < 2; mt++)
                        ldm_x4(afr[mt], pa + (uint32_t)mt * 1280u + (uint32_t)k16 * 32u);
                    uint32_t bfr[2][4];
                    #pragma unroll
                    for (int np = 0; np < 2; np++)
                        ldm_x4_t(bfr[np], hb + (uint32_t)k16 * 4352u + (uint32_t)np * 32u);
                    #pragma unroll
                    for (int mt = 0; mt < 2; mt++)
                        #pragma unroll
                        for (int nt = 0; nt < 4; nt++)
                            mma_f16(acc[mt][nt], afr[mt], &bfr[nt >> 1][(nt & 1) * 2]);
                }
            }
            bar_arrive_n(3 + slot, 768);
        }

        __syncthreads();

        #pragma unroll
        for (int mt = 0; mt < 2; mt++) {
            const int rl0 = wm * 32 + mt * 16 + gq;
            const float zi0 = 1.0f / Zs[rl0];
            const float zi1 = 1.0f / Zs[rl0 + 8];
            const int r = m0 + rl0;
            #pragma unroll
            for (int nt = 0; nt < 4; nt++) {
                const int c = wn * 32 + nt * 8 + tg * 2;
                *(float2*)&out[(size_t)r * OUT_F + c] =
                    make_float2(acc[mt][nt][0] * zi0, acc[mt][nt][1] * zi0);
                *(float2*)&out[(size_t)(r + 8) * OUT_F + c] =
                    make_float2(acc[mt][nt][2] * zi1, acc[mt][nt][3] * zi1);
            }
        }
        return;
    }
    __syncthreads();
}

// ============================ launch =============================
extern "C" void kernel_launch(void* const* d_in, const int* in_sizes, int n_in,
                              void* d_out, int out_size) {
    const float *x = nullptr, *adj = nullptr, *W = nullptr, *a = nullptr;
    for (int i = 0; i < n_in; i++) {
        switch (in_sizes[i]) {
            case N_NODES * IN_F:  x   = (const float*)d_in[i]; break;
            case 67108864:        adj = (const float*)d_in[i]; break;
            case IN_F * OUT_F:    W   = (const float*)d_in[i]; break;
            case 2 * OUT_F:       a   = (const float*)d_in[i]; break;
            default: break;
        }
    }
    if (!x)   x   = (const float*)d_in[0];
    if (!adj) adj = (const float*)d_in[1];
    if (!W)   W   = (const float*)d_in[2];
    if (!a)   a   = (const float*)d_in[3];
    float* out = (float*)d_out;

    h_gemm_kernel<<<N_NODES / 32, 256>>>(x, W, a);

    cudaFuncSetAttribute(gat_mma_kernel, cudaFuncAttributeMaxDynamicSharedMemorySize, SMEM_SZ);
    gat_mma_kernel<<<N_NODES / 64, 768, SMEM_SZ>>>(adj, out);
}